// round 12
// baseline (speedup 1.0000x reference)
#include <cuda_runtime.h>

#define NQ 65536   // queries
#define DD 128     // dims
#define KK 1024    // codes
#define KC 8       // dims per stage
#define NSTAGE 16  // stages per code-block (KC*NSTAGE = DD)
#define ADSTR 130  // ull per A k-row (128 + pad), row = 1040B (16B-aligned)
#define BSTR 132   // floats per B k-row (128 + pad), row = 528B (16B-aligned)

typedef unsigned long long ull;

__device__ __forceinline__ void fma2(ull& d, ull a, ull b) {
    asm("fma.rn.f32x2 %0, %1, %2, %0;" : "+l"(d) : "l"(a), "l"(b));
}
__device__ __forceinline__ ull dup2(float a) {
    ull r;
    asm("mov.b64 %0, {%1, %1};" : "=l"(r) : "f"(a));
    return r;
}
__device__ __forceinline__ void unpack2(ull v, float& lo, float& hi) {
    asm("mov.b64 {%0, %1}, %2;" : "=f"(lo), "=f"(hi) : "l"(v));
}

// 256 threads = 16 tx * 16 ty. Thread tile: 8 queries {ty*4+i, 64+ty*4+i}
// x 8 codes {tx*4+j, 64+tx*4+j}. CTA: 128 queries x 1024 codes (8 blocks).
__global__ __launch_bounds__(256, 2) void vq_kernel(
    const float* __restrict__ z, const float* __restrict__ cb,
    float* __restrict__ out) {
    __shared__ ull   As[2][KC][ADSTR];  // A values pre-duplicated (a,a)
    __shared__ float Bs[2][KC][BSTR];
    __shared__ float c2s[KK];
    __shared__ float z2s[128];

    const int tid = threadIdx.x;
    const int tx = tid & 15;
    const int ty = tid >> 4;
    const int q0 = blockIdx.x * 128;
    const int srow = tid >> 1;           // staging row 0..127
    const int sh = (tid & 1) * 4;        // staging dim half offset 0|4

    // ---- c2s: ||c||^2 for all codes
#pragma unroll
    for (int j = 0; j < 4; ++j) {
        const int c = tid + j * 256;
        float s = 0.f;
#pragma unroll 8
        for (int k4 = 0; k4 < 32; ++k4) {
            const float4 v =
                *reinterpret_cast<const float4*>(&cb[c * DD + k4 * 4]);
            s = fmaf(v.x, v.x, s); s = fmaf(v.y, v.y, s);
            s = fmaf(v.z, v.z, s); s = fmaf(v.w, v.w, s);
        }
        c2s[c] = s;
    }
    // ---- z2s: ||z||^2 (only for the reference's ulp-grid tie-break)
    if (tid < 128) {
        float s = 0.f;
#pragma unroll 8
        for (int k4 = 0; k4 < 32; ++k4) {
            const float4 v = *reinterpret_cast<const float4*>(
                &z[(q0 + tid) * DD + k4 * 4]);
            s = fmaf(v.x, v.x, s); s = fmaf(v.y, v.y, s);
            s = fmaf(v.z, v.z, s); s = fmaf(v.w, v.w, s);
        }
        z2s[tid] = s;
    }

    float v0[8], v1[8];
    int i0[8], i1[8];
#pragma unroll
    for (int q = 0; q < 8; ++q) {
        v0[q] = 3.4e38f; v1[q] = 3.4e38f; i0[q] = 0; i1[q] = 0;
    }

    for (int cblk = 0; cblk < 8; ++cblk) {
        ull acc[8][4];
#pragma unroll
        for (int q = 0; q < 8; ++q)
#pragma unroll
            for (int p = 0; p < 4; ++p) acc[q][p] = 0ull;

        // ---- prologue: stage 0 into buffer 0
        float4 va = *reinterpret_cast<const float4*>(&z[(q0 + srow) * DD + sh]);
        float4 vb = *reinterpret_cast<const float4*>(
            &cb[(cblk * 128 + srow) * DD + sh]);
        __syncthreads();  // covers c2s/z2s on first entry; buffer reuse after
        As[0][sh + 0][srow] = dup2(va.x);
        As[0][sh + 1][srow] = dup2(va.y);
        As[0][sh + 2][srow] = dup2(va.z);
        As[0][sh + 3][srow] = dup2(va.w);
        Bs[0][sh + 0][srow] = vb.x;
        Bs[0][sh + 1][srow] = vb.y;
        Bs[0][sh + 2][srow] = vb.z;
        Bs[0][sh + 3][srow] = vb.w;
        __syncthreads();

        for (int kc = 0; kc < NSTAGE; ++kc) {
            const int bu = kc & 1;
            if (kc + 1 < NSTAGE) {  // prefetch next stage (hidden under compute)
                va = *reinterpret_cast<const float4*>(
                    &z[(q0 + srow) * DD + (kc + 1) * KC + sh]);
                vb = *reinterpret_cast<const float4*>(
                    &cb[(cblk * 128 + srow) * DD + (kc + 1) * KC + sh]);
            }

#pragma unroll
            for (int k = 0; k < KC; ++k) {
                const ulonglong2 a01 =
                    *reinterpret_cast<const ulonglong2*>(&As[bu][k][ty * 4]);
                const ulonglong2 a23 = *reinterpret_cast<const ulonglong2*>(
                    &As[bu][k][ty * 4 + 2]);
                const ulonglong2 a45 = *reinterpret_cast<const ulonglong2*>(
                    &As[bu][k][64 + ty * 4]);
                const ulonglong2 a67 = *reinterpret_cast<const ulonglong2*>(
                    &As[bu][k][64 + ty * 4 + 2]);
                const ulonglong2 b01 =
                    *reinterpret_cast<const ulonglong2*>(&Bs[bu][k][tx * 4]);
                const ulonglong2 b23 = *reinterpret_cast<const ulonglong2*>(
                    &Bs[bu][k][64 + tx * 4]);
                fma2(acc[0][0], a01.x, b01.x); fma2(acc[0][1], a01.x, b01.y);
                fma2(acc[0][2], a01.x, b23.x); fma2(acc[0][3], a01.x, b23.y);
                fma2(acc[1][0], a01.y, b01.x); fma2(acc[1][1], a01.y, b01.y);
                fma2(acc[1][2], a01.y, b23.x); fma2(acc[1][3], a01.y, b23.y);
                fma2(acc[2][0], a23.x, b01.x); fma2(acc[2][1], a23.x, b01.y);
                fma2(acc[2][2], a23.x, b23.x); fma2(acc[2][3], a23.x, b23.y);
                fma2(acc[3][0], a23.y, b01.x); fma2(acc[3][1], a23.y, b01.y);
                fma2(acc[3][2], a23.y, b23.x); fma2(acc[3][3], a23.y, b23.y);
                fma2(acc[4][0], a45.x, b01.x); fma2(acc[4][1], a45.x, b01.y);
                fma2(acc[4][2], a45.x, b23.x); fma2(acc[4][3], a45.x, b23.y);
                fma2(acc[5][0], a45.y, b01.x); fma2(acc[5][1], a45.y, b01.y);
                fma2(acc[5][2], a45.y, b23.x); fma2(acc[5][3], a45.y, b23.y);
                fma2(acc[6][0], a67.x, b01.x); fma2(acc[6][1], a67.x, b01.y);
                fma2(acc[6][2], a67.x, b23.x); fma2(acc[6][3], a67.x, b23.y);
                fma2(acc[7][0], a67.y, b01.x); fma2(acc[7][1], a67.y, b01.y);
                fma2(acc[7][2], a67.y, b23.x); fma2(acc[7][3], a67.y, b23.y);
            }

            if (kc + 1 < NSTAGE) {
                const int nb = bu ^ 1;
                As[nb][sh + 0][srow] = dup2(va.x);
                As[nb][sh + 1][srow] = dup2(va.y);
                As[nb][sh + 2][srow] = dup2(va.z);
                As[nb][sh + 3][srow] = dup2(va.w);
                Bs[nb][sh + 0][srow] = vb.x;
                Bs[nb][sh + 1][srow] = vb.y;
                Bs[nb][sh + 2][srow] = vb.z;
                Bs[nb][sh + 3][srow] = vb.w;
            }
            __syncthreads();
        }

        // ---- scores; ascending code order per query (first-occurrence top-2)
        const int cbase = cblk * 128;
#pragma unroll
        for (int q = 0; q < 8; ++q) {
#pragma unroll
            for (int p = 0; p < 4; ++p) {
                const int cc = cbase + ((p < 2) ? (tx * 4 + p * 2)
                                                : (64 + tx * 4 + (p - 2) * 2));
                float dlo, dhi;
                unpack2(acc[q][p], dlo, dhi);
                const float mlo = fmaf(-2.f, dlo, c2s[cc]);
                const float mhi = fmaf(-2.f, dhi, c2s[cc + 1]);
                if (mlo < v0[q]) {
                    v1[q] = v0[q]; i1[q] = i0[q]; v0[q] = mlo; i0[q] = cc;
                } else if (mlo < v1[q]) { v1[q] = mlo; i1[q] = cc; }
                if (mhi < v0[q]) {
                    v1[q] = v0[q]; i1[q] = i0[q]; v0[q] = mhi; i0[q] = cc + 1;
                } else if (mhi < v1[q]) { v1[q] = mhi; i1[q] = cc + 1; }
            }
        }
    }

    // ---- merge top-2 across the 16 tx lanes
#pragma unroll
    for (int off = 1; off < 16; off <<= 1) {
#pragma unroll
        for (int q = 0; q < 8; ++q) {
            const float w0 = __shfl_xor_sync(0xffffffffu, v0[q], off);
            const int j0 = __shfl_xor_sync(0xffffffffu, i0[q], off);
            const float w1 = __shfl_xor_sync(0xffffffffu, v1[q], off);
            const int j1 = __shfl_xor_sync(0xffffffffu, i1[q], off);
            if (w0 < v0[q] || (w0 == v0[q] && j0 < i0[q])) {
                v1[q] = v0[q]; i1[q] = i0[q]; v0[q] = w0; i0[q] = j0;
            } else if (w0 < v1[q] || (w0 == v1[q] && j0 < i1[q])) {
                v1[q] = w0; i1[q] = j0;
            }
            if (w1 < v0[q] || (w1 == v0[q] && j1 < i0[q])) {
                v1[q] = v0[q]; i1[q] = i0[q]; v0[q] = w1; i0[q] = j1;
            } else if (w1 < v1[q] || (w1 == v1[q] && j1 < i1[q])) {
                v1[q] = w1; i1[q] = j1;
            }
        }
    }

    if (tx == 0) {
#pragma unroll
        for (int q = 0; q < 8; ++q) {
            const int lq = (q < 4) ? (ty * 4 + q) : (64 + ty * 4 + (q - 4));
            // Reference dist2 = (z2-2dot)+c2 is quantized at ulp(z2+score):
            // within one grid step the reference ties -> argmin picks lower idx.
            const float sfull = z2s[lq] + v0[q];
            const int ebits = (__float_as_int(sfull) >> 23) & 0xff;
            const float u = __int_as_float((ebits - 23) << 23);
            int win = i0[q];
            if (v1[q] - v0[q] <= u && i1[q] < i0[q]) win = i1[q];
            out[q0 + lq] = (float)win;
        }
    }
}

extern "C" void kernel_launch(void* const* d_in, const int* in_sizes, int n_in,
                              void* d_out, int out_size) {
    const float* z  = (const float*)d_in[0];
    const float* cb = (const float*)d_in[1];
    if (n_in >= 2 && in_sizes[0] == KK * DD) {  // defensive order check
        cb = (const float*)d_in[0];
        z  = (const float*)d_in[1];
    }
    vq_kernel<<<NQ / 128, 256>>>(z, cb, (float*)d_out);
}

// round 14
// speedup vs baseline: 1.0138x; 1.0138x over previous
#include <cuda_runtime.h>

#define NQ 65536   // queries
#define DD 128     // dims
#define KK 1024    // codes
#define ADSTR 130  // ull per As k-row (128 + pad); even => LDS.128 stays 16B-aligned
#define BSTR 132   // floats per Bs k-row (128 + pad)

typedef unsigned long long ull;

__device__ __forceinline__ void fma2(ull& d, ull a, ull b) {
    asm("fma.rn.f32x2 %0, %1, %2, %0;" : "+l"(d) : "l"(a), "l"(b));
}
__device__ __forceinline__ ull dup2(float a) {
    ull r;
    asm("mov.b64 %0, {%1, %1};" : "=l"(r) : "f"(a));
    return r;
}
__device__ __forceinline__ void unpack2(ull v, float& lo, float& hi) {
    asm("mov.b64 {%0, %1}, %2;" : "=f"(lo), "=f"(hi) : "l"(v));
}

// R8 skeleton (best known): 256 threads = 16 tx * 16 ty.
// Thread tile: 8 queries {ty*4+i, 64+ty*4+i} x 8 codes {tx*4+j, 64+tx*4+j}.
// CTA: 128 queries x 1024 codes (8 blocks of 128), dims staged 16 at a time.
// ONE change vs R8: As holds pre-duplicated (a,a) packed pairs -> no dup movs
// in the k-loop (44 -> 38 issue slots per k-iteration).
__global__ __launch_bounds__(256, 2) void vq_kernel(
    const float* __restrict__ z, const float* __restrict__ cb,
    float* __restrict__ out) {
    __shared__ ull   As[16 * ADSTR];  // [k][q] pre-duplicated query tile
    __shared__ float Bs[16 * BSTR];   // [k][c] code tile
    __shared__ float c2s[KK];
    __shared__ float z2s[128];

    const int tid = threadIdx.x;
    const int tx = tid & 15;
    const int ty = tid >> 4;
    const int q0 = blockIdx.x * 128;

    // ---- c2s: ||c||^2 for all 1024 codes (4 per thread)
#pragma unroll
    for (int j = 0; j < 4; ++j) {
        const int c = tid + j * 256;
        float s = 0.f;
#pragma unroll 8
        for (int k4 = 0; k4 < 32; ++k4) {
            const float4 v =
                *reinterpret_cast<const float4*>(&cb[c * DD + k4 * 4]);
            s = fmaf(v.x, v.x, s); s = fmaf(v.y, v.y, s);
            s = fmaf(v.z, v.z, s); s = fmaf(v.w, v.w, s);
        }
        c2s[c] = s;
    }
    // ---- z2s: ||z||^2 (only for the reference's ulp-grid tie-break)
    if (tid < 128) {
        float s = 0.f;
#pragma unroll 8
        for (int k4 = 0; k4 < 32; ++k4) {
            const float4 v = *reinterpret_cast<const float4*>(
                &z[(q0 + tid) * DD + k4 * 4]);
            s = fmaf(v.x, v.x, s); s = fmaf(v.y, v.y, s);
            s = fmaf(v.z, v.z, s); s = fmaf(v.w, v.w, s);
        }
        z2s[tid] = s;
    }

    float v0[8], v1[8];
    int i0[8], i1[8];
#pragma unroll
    for (int q = 0; q < 8; ++q) {
        v0[q] = 3.4e38f; v1[q] = 3.4e38f; i0[q] = 0; i1[q] = 0;
    }

    for (int cblk = 0; cblk < 8; ++cblk) {
        ull acc[8][4];
#pragma unroll
        for (int q = 0; q < 8; ++q)
#pragma unroll
            for (int p = 0; p < 4; ++p) acc[q][p] = 0ull;

        for (int kc = 0; kc < 8; ++kc) {
            __syncthreads();  // prior readers done (covers c2s/z2s at first)
            // Stage As/Bs: 128 rows x 16 dims each, transposed to [k][row].
            // As gets pre-duplicated (a,a) packed values.
#pragma unroll
            for (int i = 0; i < 2; ++i) {
                const int idx = tid + i * 256;       // 0..511
                const int row = idx >> 2, d4 = idx & 3;
                const float4 va = *reinterpret_cast<const float4*>(
                    &z[(q0 + row) * DD + kc * 16 + d4 * 4]);
                As[(d4 * 4 + 0) * ADSTR + row] = dup2(va.x);
                As[(d4 * 4 + 1) * ADSTR + row] = dup2(va.y);
                As[(d4 * 4 + 2) * ADSTR + row] = dup2(va.z);
                As[(d4 * 4 + 3) * ADSTR + row] = dup2(va.w);
                const float4 vb = *reinterpret_cast<const float4*>(
                    &cb[(cblk * 128 + row) * DD + kc * 16 + d4 * 4]);
                Bs[(d4 * 4 + 0) * BSTR + row] = vb.x;
                Bs[(d4 * 4 + 1) * BSTR + row] = vb.y;
                Bs[(d4 * 4 + 2) * BSTR + row] = vb.z;
                Bs[(d4 * 4 + 3) * BSTR + row] = vb.w;
            }
            __syncthreads();

#pragma unroll 4
            for (int k = 0; k < 16; ++k) {
                const ulonglong2 a01 = *reinterpret_cast<const ulonglong2*>(
                    &As[k * ADSTR + ty * 4]);
                const ulonglong2 a23 = *reinterpret_cast<const ulonglong2*>(
                    &As[k * ADSTR + ty * 4 + 2]);
                const ulonglong2 a45 = *reinterpret_cast<const ulonglong2*>(
                    &As[k * ADSTR + 64 + ty * 4]);
                const ulonglong2 a67 = *reinterpret_cast<const ulonglong2*>(
                    &As[k * ADSTR + 64 + ty * 4 + 2]);
                const ulonglong2 b01 = *reinterpret_cast<const ulonglong2*>(
                    &Bs[k * BSTR + tx * 4]);
                const ulonglong2 b23 = *reinterpret_cast<const ulonglong2*>(
                    &Bs[k * BSTR + 64 + tx * 4]);
                fma2(acc[0][0], a01.x, b01.x); fma2(acc[0][1], a01.x, b01.y);
                fma2(acc[0][2], a01.x, b23.x); fma2(acc[0][3], a01.x, b23.y);
                fma2(acc[1][0], a01.y, b01.x); fma2(acc[1][1], a01.y, b01.y);
                fma2(acc[1][2], a01.y, b23.x); fma2(acc[1][3], a01.y, b23.y);
                fma2(acc[2][0], a23.x, b01.x); fma2(acc[2][1], a23.x, b01.y);
                fma2(acc[2][2], a23.x, b23.x); fma2(acc[2][3], a23.x, b23.y);
                fma2(acc[3][0], a23.y, b01.x); fma2(acc[3][1], a23.y, b01.y);
                fma2(acc[3][2], a23.y, b23.x); fma2(acc[3][3], a23.y, b23.y);
                fma2(acc[4][0], a45.x, b01.x); fma2(acc[4][1], a45.x, b01.y);
                fma2(acc[4][2], a45.x, b23.x); fma2(acc[4][3], a45.x, b23.y);
                fma2(acc[5][0], a45.y, b01.x); fma2(acc[5][1], a45.y, b01.y);
                fma2(acc[5][2], a45.y, b23.x); fma2(acc[5][3], a45.y, b23.y);
                fma2(acc[6][0], a67.x, b01.x); fma2(acc[6][1], a67.x, b01.y);
                fma2(acc[6][2], a67.x, b23.x); fma2(acc[6][3], a67.x, b23.y);
                fma2(acc[7][0], a67.y, b01.x); fma2(acc[7][1], a67.y, b01.y);
                fma2(acc[7][2], a67.y, b23.x); fma2(acc[7][3], a67.y, b23.y);
            }
        }

        // ---- scores; ascending code order per query (first-occurrence top-2)
        const int cbase = cblk * 128;
#pragma unroll
        for (int q = 0; q < 8; ++q) {
#pragma unroll
            for (int p = 0; p < 4; ++p) {
                const int cc = cbase + ((p < 2) ? (tx * 4 + p * 2)
                                                : (64 + tx * 4 + (p - 2) * 2));
                float dlo, dhi;
                unpack2(acc[q][p], dlo, dhi);
                const float mlo = fmaf(-2.f, dlo, c2s[cc]);
                const float mhi = fmaf(-2.f, dhi, c2s[cc + 1]);
                if (mlo < v0[q]) {
                    v1[q] = v0[q]; i1[q] = i0[q]; v0[q] = mlo; i0[q] = cc;
                } else if (mlo < v1[q]) { v1[q] = mlo; i1[q] = cc; }
                if (mhi < v0[q]) {
                    v1[q] = v0[q]; i1[q] = i0[q]; v0[q] = mhi; i0[q] = cc + 1;
                } else if (mhi < v1[q]) { v1[q] = mhi; i1[q] = cc + 1; }
            }
        }
    }

    // ---- merge top-2 across the 16 tx lanes
#pragma unroll
    for (int off = 1; off < 16; off <<= 1) {
#pragma unroll
        for (int q = 0; q < 8; ++q) {
            const float w0 = __shfl_xor_sync(0xffffffffu, v0[q], off);
            const int j0 = __shfl_xor_sync(0xffffffffu, i0[q], off);
            const float w1 = __shfl_xor_sync(0xffffffffu, v1[q], off);
            const int j1 = __shfl_xor_sync(0xffffffffu, i1[q], off);
            if (w0 < v0[q] || (w0 == v0[q] && j0 < i0[q])) {
                v1[q] = v0[q]; i1[q] = i0[q]; v0[q] = w0; i0[q] = j0;
            } else if (w0 < v1[q] || (w0 == v1[q] && j0 < i1[q])) {
                v1[q] = w0; i1[q] = j0;
            }
            if (w1 < v0[q] || (w1 == v0[q] && j1 < i0[q])) {
                v1[q] = v0[q]; i1[q] = i0[q]; v0[q] = w1; i0[q] = j1;
            } else if (w1 < v1[q] || (w1 == v1[q] && j1 < i1[q])) {
                v1[q] = w1; i1[q] = j1;
            }
        }
    }

    if (tx == 0) {
#pragma unroll
        for (int q = 0; q < 8; ++q) {
            const int lq = (q < 4) ? (ty * 4 + q) : (64 + ty * 4 + (q - 4));
            // Reference dist2 = (z2-2dot)+c2 quantized at ulp(z2+score):
            // within one grid step the reference ties -> argmin picks lower idx.
            const float sfull = z2s[lq] + v0[q];
            const int ebits = (__float_as_int(sfull) >> 23) & 0xff;
            const float u = __int_as_float((ebits - 23) << 23);
            int win = i0[q];
            if (v1[q] - v0[q] <= u && i1[q] < i0[q]) win = i1[q];
            out[q0 + lq] = (float)win;
        }
    }
}

extern "C" void kernel_launch(void* const* d_in, const int* in_sizes, int n_in,
                              void* d_out, int out_size) {
    const float* z  = (const float*)d_in[0];
    const float* cb = (const float*)d_in[1];
    if (n_in >= 2 && in_sizes[0] == KK * DD) {  // defensive order check
        cb = (const float*)d_in[0];
        z  = (const float*)d_in[1];
    }
    vq_kernel<<<NQ / 128, 256>>>(z, cb, (float*)d_out);
}

// round 15
// speedup vs baseline: 1.0901x; 1.0752x over previous
#include <cuda_runtime.h>

#define NQ 65536   // queries
#define DD 128     // dims
#define KK 1024    // codes
#define KC 16      // dims per stage
#define NST 8      // stages per code-block (KC*NST = DD)
#define ASTR 132   // floats per smem k-row (128 + pad)

typedef unsigned long long ull;

__device__ __forceinline__ void fma2(ull& d, ull a, ull b) {
    asm("fma.rn.f32x2 %0, %1, %2, %0;" : "+l"(d) : "l"(a), "l"(b));
}
__device__ __forceinline__ ull dup2(float a) {
    ull r;
    asm("mov.b64 %0, {%1, %1};" : "=l"(r) : "f"(a));
    return r;
}
__device__ __forceinline__ void unpack2(ull v, float& lo, float& hi) {
    asm("mov.b64 {%0, %1}, %2;" : "=f"(lo), "=f"(hi) : "l"(v));
}

// R8 inner loop verbatim (raw A + dup movs: ALU-pipe cheap, LSU untouched).
// CHANGE vs R8: double-buffered staging, LDG prefetched UNDER compute,
// ONE barrier per stage (16 -> 9 barriers per cblk, LDG latency hidden).
// 256 threads = 16 tx * 16 ty; thread tile 8q x 8c; CTA 128q x 1024c.
__global__ __launch_bounds__(256, 2) void vq_kernel(
    const float* __restrict__ z, const float* __restrict__ cb,
    float* __restrict__ out) {
    __shared__ float As[2][KC][ASTR];  // [buf][k][q]
    __shared__ float Bs[2][KC][ASTR];  // [buf][k][c]
    __shared__ float c2s[KK];
    __shared__ float z2s[128];

    const int tid = threadIdx.x;
    const int tx = tid & 15;
    const int ty = tid >> 4;
    const int q0 = blockIdx.x * 128;

    // ---- c2s: ||c||^2 for all 1024 codes (4 per thread)
#pragma unroll
    for (int j = 0; j < 4; ++j) {
        const int c = tid + j * 256;
        float s = 0.f;
#pragma unroll 8
        for (int k4 = 0; k4 < 32; ++k4) {
            const float4 v =
                *reinterpret_cast<const float4*>(&cb[c * DD + k4 * 4]);
            s = fmaf(v.x, v.x, s); s = fmaf(v.y, v.y, s);
            s = fmaf(v.z, v.z, s); s = fmaf(v.w, v.w, s);
        }
        c2s[c] = s;
    }
    // ---- z2s: ||z||^2 (only for the reference's ulp-grid tie-break)
    if (tid < 128) {
        float s = 0.f;
#pragma unroll 8
        for (int k4 = 0; k4 < 32; ++k4) {
            const float4 v = *reinterpret_cast<const float4*>(
                &z[(q0 + tid) * DD + k4 * 4]);
            s = fmaf(v.x, v.x, s); s = fmaf(v.y, v.y, s);
            s = fmaf(v.z, v.z, s); s = fmaf(v.w, v.w, s);
        }
        z2s[tid] = s;
    }
    // (visibility of c2s/z2s is established by the staging barriers below)

    const int srow = tid >> 2;        // staging row 0..63 base (2 iters -> 128)
    const int sd4 = tid & 3;          // staging dim quad 0..3

    float v0[8], v1[8];
    int i0[8], i1[8];
#pragma unroll
    for (int q = 0; q < 8; ++q) {
        v0[q] = 3.4e38f; v1[q] = 3.4e38f; i0[q] = 0; i1[q] = 0;
    }

    for (int cblk = 0; cblk < 8; ++cblk) {
        ull acc[8][4];
#pragma unroll
        for (int q = 0; q < 8; ++q)
#pragma unroll
            for (int p = 0; p < 4; ++p) acc[q][p] = 0ull;

        float4 va[2], vb[2];
        // ---- prologue: LDG stage 0, STS into buf 0.
        // Safe without a pre-barrier: all warps passed the previous cblk's
        // final stage barrier before reaching here.
#pragma unroll
        for (int i = 0; i < 2; ++i) {
            const int row = srow + i * 64;
            va[i] = *reinterpret_cast<const float4*>(
                &z[(q0 + row) * DD + sd4 * 4]);
            vb[i] = *reinterpret_cast<const float4*>(
                &cb[(cblk * 128 + row) * DD + sd4 * 4]);
        }
#pragma unroll
        for (int i = 0; i < 2; ++i) {
            const int row = srow + i * 64;
            As[0][sd4 * 4 + 0][row] = va[i].x;
            As[0][sd4 * 4 + 1][row] = va[i].y;
            As[0][sd4 * 4 + 2][row] = va[i].z;
            As[0][sd4 * 4 + 3][row] = va[i].w;
            Bs[0][sd4 * 4 + 0][row] = vb[i].x;
            Bs[0][sd4 * 4 + 1][row] = vb[i].y;
            Bs[0][sd4 * 4 + 2][row] = vb[i].z;
            Bs[0][sd4 * 4 + 3][row] = vb[i].w;
        }
        __syncthreads();

        for (int kc = 0; kc < NST; ++kc) {
            const int bu = kc & 1;
            // ---- prefetch next stage's data (latency hidden under compute)
            if (kc + 1 < NST) {
#pragma unroll
                for (int i = 0; i < 2; ++i) {
                    const int row = srow + i * 64;
                    va[i] = *reinterpret_cast<const float4*>(
                        &z[(q0 + row) * DD + (kc + 1) * KC + sd4 * 4]);
                    vb[i] = *reinterpret_cast<const float4*>(
                        &cb[(cblk * 128 + row) * DD + (kc + 1) * KC + sd4 * 4]);
                }
            }

            // ---- compute: R8 inner loop verbatim
#pragma unroll 4
            for (int k = 0; k < KC; ++k) {
                const float4 a0 =
                    *reinterpret_cast<const float4*>(&As[bu][k][ty * 4]);
                const float4 a1 = *reinterpret_cast<const float4*>(
                    &As[bu][k][64 + ty * 4]);
                const ulonglong2 b01 =
                    *reinterpret_cast<const ulonglong2*>(&Bs[bu][k][tx * 4]);
                const ulonglong2 b23 = *reinterpret_cast<const ulonglong2*>(
                    &Bs[bu][k][64 + tx * 4]);
                const ull aa[8] = {dup2(a0.x), dup2(a0.y), dup2(a0.z),
                                   dup2(a0.w), dup2(a1.x), dup2(a1.y),
                                   dup2(a1.z), dup2(a1.w)};
                const ull bb[4] = {b01.x, b01.y, b23.x, b23.y};
#pragma unroll
                for (int q = 0; q < 8; ++q)
#pragma unroll
                    for (int p = 0; p < 4; ++p) fma2(acc[q][p], aa[q], bb[p]);
            }

            // ---- STS into the other buffer; single barrier per stage.
            if (kc + 1 < NST) {
                const int nb = bu ^ 1;
#pragma unroll
                for (int i = 0; i < 2; ++i) {
                    const int row = srow + i * 64;
                    As[nb][sd4 * 4 + 0][row] = va[i].x;
                    As[nb][sd4 * 4 + 1][row] = va[i].y;
                    As[nb][sd4 * 4 + 2][row] = va[i].z;
                    As[nb][sd4 * 4 + 3][row] = va[i].w;
                    Bs[nb][sd4 * 4 + 0][row] = vb[i].x;
                    Bs[nb][sd4 * 4 + 1][row] = vb[i].y;
                    Bs[nb][sd4 * 4 + 2][row] = vb[i].z;
                    Bs[nb][sd4 * 4 + 3][row] = vb[i].w;
                }
            }
            __syncthreads();
        }

        // ---- scores; ascending code order per query (first-occurrence top-2)
        const int cbase = cblk * 128;
#pragma unroll
        for (int q = 0; q < 8; ++q) {
#pragma unroll
            for (int p = 0; p < 4; ++p) {
                const int cc = cbase + ((p < 2) ? (tx * 4 + p * 2)
                                                : (64 + tx * 4 + (p - 2) * 2));
                float dlo, dhi;
                unpack2(acc[q][p], dlo, dhi);
                const float mlo = fmaf(-2.f, dlo, c2s[cc]);
                const float mhi = fmaf(-2.f, dhi, c2s[cc + 1]);
                if (mlo < v0[q]) {
                    v1[q] = v0[q]; i1[q] = i0[q]; v0[q] = mlo; i0[q] = cc;
                } else if (mlo < v1[q]) { v1[q] = mlo; i1[q] = cc; }
                if (mhi < v0[q]) {
                    v1[q] = v0[q]; i1[q] = i0[q]; v0[q] = mhi; i0[q] = cc + 1;
                } else if (mhi < v1[q]) { v1[q] = mhi; i1[q] = cc + 1; }
            }
        }
    }

    // ---- merge top-2 across the 16 tx lanes
#pragma unroll
    for (int off = 1; off < 16; off <<= 1) {
#pragma unroll
        for (int q = 0; q < 8; ++q) {
            const float w0 = __shfl_xor_sync(0xffffffffu, v0[q], off);
            const int j0 = __shfl_xor_sync(0xffffffffu, i0[q], off);
            const float w1 = __shfl_xor_sync(0xffffffffu, v1[q], off);
            const int j1 = __shfl_xor_sync(0xffffffffu, i1[q], off);
            if (w0 < v0[q] || (w0 == v0[q] && j0 < i0[q])) {
                v1[q] = v0[q]; i1[q] = i0[q]; v0[q] = w0; i0[q] = j0;
            } else if (w0 < v1[q] || (w0 == v1[q] && j0 < i1[q])) {
                v1[q] = w0; i1[q] = j0;
            }
            if (w1 < v0[q] || (w1 == v0[q] && j1 < i0[q])) {
                v1[q] = v0[q]; i1[q] = i0[q]; v0[q] = w1; i0[q] = j1;
            } else if (w1 < v1[q] || (w1 == v1[q] && j1 < i1[q])) {
                v1[q] = w1; i1[q] = j1;
            }
        }
    }

    if (tx == 0) {
#pragma unroll
        for (int q = 0; q < 8; ++q) {
            const int lq = (q < 4) ? (ty * 4 + q) : (64 + ty * 4 + (q - 4));
            // Reference dist2 = (z2-2dot)+c2 quantized at ulp(z2+score):
            // within one grid step the reference ties -> argmin picks lower idx.
            const float sfull = z2s[lq] + v0[q];
            const int ebits = (__float_as_int(sfull) >> 23) & 0xff;
            const float u = __int_as_float((ebits - 23) << 23);
            int win = i0[q];
            if (v1[q] - v0[q] <= u && i1[q] < i0[q]) win = i1[q];
            out[q0 + lq] = (float)win;
        }
    }
}

extern "C" void kernel_launch(void* const* d_in, const int* in_sizes, int n_in,
                              void* d_out, int out_size) {
    const float* z  = (const float*)d_in[0];
    const float* cb = (const float*)d_in[1];
    if (n_in >= 2 && in_sizes[0] == KK * DD) {  // defensive order check
        cb = (const float*)d_in[0];
        z  = (const float*)d_in[1];
    }
    vq_kernel<<<NQ / 128, 256>>>(z, cb, (float*)d_out);
}

// round 16
// speedup vs baseline: 1.1185x; 1.0260x over previous
#include <cuda_runtime.h>

#define NQ 65536   // queries
#define DD 128     // dims
#define KK 1024    // codes
#define KC 16      // dims per Bs stage
#define NST 8      // stages (KC*NST = DD)
#define NCB 16     // code blocks of 64
#define AFS 68     // As_full row stride (floats); 68*4B = 272B, 16B-aligned
#define BFS 68     // Bs row stride

typedef unsigned long long ull;

__device__ __forceinline__ void fma2(ull& d, ull a, ull b) {
    asm("fma.rn.f32x2 %0, %1, %2, %0;" : "+l"(d) : "l"(a), "l"(b));
}
__device__ __forceinline__ ull dup2(float a) {
    ull r;
    asm("mov.b64 %0, {%1, %1};" : "=l"(r) : "f"(a));
    return r;
}
__device__ __forceinline__ void unpack2(ull v, float& lo, float& hi) {
    asm("mov.b64 {%0, %1}, %2;" : "=f"(lo), "=f"(hi) : "l"(v));
}

// R16: occupancy + staging attack.
// 256 threads = 16 tx * 16 ty. Thread tile: 4 queries (ty*4+i) x 4 codes
// (tx*4+j). CTA = 64 queries x 1024 codes (16 blocks of 64).
// A tile (64q x 128d) resident in smem for the whole kernel; only Bs
// (64c x 16d) double-buffers. Smem 47.8KB static; 3 CTAs/SM (24 warps).
__global__ __launch_bounds__(256, 3) void vq_kernel(
    const float* __restrict__ z, const float* __restrict__ cb,
    float* __restrict__ out) {
    __shared__ float Af[DD * AFS];        // [dim][q] resident query tile, 34.8K
    __shared__ float Bs[2][KC * BFS];     // [buf][dim][c] staged code tile
    __shared__ float c2s[KK];
    __shared__ float z2s[64];

    const int tid = threadIdx.x;
    const int tx = tid & 15;
    const int ty = tid >> 4;
    const int q0 = blockIdx.x * 64;

    // ---- Resident A tile: 64q x 128d, transposed to [dim][q]. 8 f4/thread.
#pragma unroll
    for (int i = 0; i < 8; ++i) {
        const int idx = tid + i * 256;            // 0..2047
        const int row = idx >> 5, d4 = idx & 31;  // q, dim-quad
        const float4 v =
            *reinterpret_cast<const float4*>(&z[(q0 + row) * DD + d4 * 4]);
        Af[(d4 * 4 + 0) * AFS + row] = v.x;
        Af[(d4 * 4 + 1) * AFS + row] = v.y;
        Af[(d4 * 4 + 2) * AFS + row] = v.z;
        Af[(d4 * 4 + 3) * AFS + row] = v.w;
    }
    // ---- c2s: ||c||^2 for all 1024 codes (4 per thread)
#pragma unroll
    for (int j = 0; j < 4; ++j) {
        const int c = tid + j * 256;
        float s = 0.f;
#pragma unroll 8
        for (int k4 = 0; k4 < 32; ++k4) {
            const float4 v =
                *reinterpret_cast<const float4*>(&cb[c * DD + k4 * 4]);
            s = fmaf(v.x, v.x, s); s = fmaf(v.y, v.y, s);
            s = fmaf(v.z, v.z, s); s = fmaf(v.w, v.w, s);
        }
        c2s[c] = s;
    }
    // ---- z2s: ||z||^2 (only for the reference's ulp-grid tie-break)
    if (tid < 64) {
        float s = 0.f;
#pragma unroll 8
        for (int k4 = 0; k4 < 32; ++k4) {
            const float4 v = *reinterpret_cast<const float4*>(
                &z[(q0 + tid) * DD + k4 * 4]);
            s = fmaf(v.x, v.x, s); s = fmaf(v.y, v.y, s);
            s = fmaf(v.z, v.z, s); s = fmaf(v.w, v.w, s);
        }
        z2s[tid] = s;
    }

    const int scode = tid >> 2;   // staging code 0..63
    const int sd4 = tid & 3;      // staging dim quad 0..3

    float v0[4], v1[4];
    int i0[4], i1[4];
#pragma unroll
    for (int q = 0; q < 4; ++q) {
        v0[q] = 3.4e38f; v1[q] = 3.4e38f; i0[q] = 0; i1[q] = 0;
    }

    for (int cblk = 0; cblk < NCB; ++cblk) {
        const int cb0 = cblk * 64;
        ull acc[4][2];
#pragma unroll
        for (int q = 0; q < 4; ++q) { acc[q][0] = 0ull; acc[q][1] = 0ull; }

        // ---- prologue: stage 0 -> buf 0 (prev cblk's last barrier protects)
        float4 vb = *reinterpret_cast<const float4*>(
            &cb[(cb0 + scode) * DD + sd4 * 4]);
        Bs[0][(sd4 * 4 + 0) * BFS + scode] = vb.x;
        Bs[0][(sd4 * 4 + 1) * BFS + scode] = vb.y;
        Bs[0][(sd4 * 4 + 2) * BFS + scode] = vb.z;
        Bs[0][(sd4 * 4 + 3) * BFS + scode] = vb.w;
        __syncthreads();  // also covers Af/c2s/z2s on first iteration

        for (int kc = 0; kc < NST; ++kc) {
            const int bu = kc & 1;
            if (kc + 1 < NST) {  // prefetch next stage under compute
                vb = *reinterpret_cast<const float4*>(
                    &cb[(cb0 + scode) * DD + (kc + 1) * KC + sd4 * 4]);
            }

#pragma unroll
            for (int k = 0; k < KC; ++k) {
                const float4 a = *reinterpret_cast<const float4*>(
                    &Af[(kc * KC + k) * AFS + ty * 4]);
                const ulonglong2 b = *reinterpret_cast<const ulonglong2*>(
                    &Bs[bu][k * BFS + tx * 4]);
                const ull a0 = dup2(a.x), a1 = dup2(a.y), a2 = dup2(a.z),
                          a3 = dup2(a.w);
                fma2(acc[0][0], a0, b.x); fma2(acc[0][1], a0, b.y);
                fma2(acc[1][0], a1, b.x); fma2(acc[1][1], a1, b.y);
                fma2(acc[2][0], a2, b.x); fma2(acc[2][1], a2, b.y);
                fma2(acc[3][0], a3, b.x); fma2(acc[3][1], a3, b.y);
            }

            if (kc + 1 < NST) {
                const int nb = bu ^ 1;
                Bs[nb][(sd4 * 4 + 0) * BFS + scode] = vb.x;
                Bs[nb][(sd4 * 4 + 1) * BFS + scode] = vb.y;
                Bs[nb][(sd4 * 4 + 2) * BFS + scode] = vb.z;
                Bs[nb][(sd4 * 4 + 3) * BFS + scode] = vb.w;
            }
            __syncthreads();
        }

        // ---- scores; ascending code order per query (first-occurrence top-2)
#pragma unroll
        for (int q = 0; q < 4; ++q) {
#pragma unroll
            for (int p = 0; p < 2; ++p) {
                const int cc = cb0 + tx * 4 + p * 2;
                float dlo, dhi;
                unpack2(acc[q][p], dlo, dhi);
                const float mlo = fmaf(-2.f, dlo, c2s[cc]);
                const float mhi = fmaf(-2.f, dhi, c2s[cc + 1]);
                if (mlo < v0[q]) {
                    v1[q] = v0[q]; i1[q] = i0[q]; v0[q] = mlo; i0[q] = cc;
                } else if (mlo < v1[q]) { v1[q] = mlo; i1[q] = cc; }
                if (mhi < v0[q]) {
                    v1[q] = v0[q]; i1[q] = i0[q]; v0[q] = mhi; i0[q] = cc + 1;
                } else if (mhi < v1[q]) { v1[q] = mhi; i1[q] = cc + 1; }
            }
        }
    }

    // ---- merge top-2 across the 16 tx lanes
#pragma unroll
    for (int off = 1; off < 16; off <<= 1) {
#pragma unroll
        for (int q = 0; q < 4; ++q) {
            const float w0 = __shfl_xor_sync(0xffffffffu, v0[q], off);
            const int j0 = __shfl_xor_sync(0xffffffffu, i0[q], off);
            const float w1 = __shfl_xor_sync(0xffffffffu, v1[q], off);
            const int j1 = __shfl_xor_sync(0xffffffffu, i1[q], off);
            if (w0 < v0[q] || (w0 == v0[q] && j0 < i0[q])) {
                v1[q] = v0[q]; i1[q] = i0[q]; v0[q] = w0; i0[q] = j0;
            } else if (w0 < v1[q] || (w0 == v1[q] && j0 < i1[q])) {
                v1[q] = w0; i1[q] = j0;
            }
            if (w1 < v0[q] || (w1 == v0[q] && j1 < i0[q])) {
                v1[q] = v0[q]; i1[q] = i0[q]; v0[q] = w1; i0[q] = j1;
            } else if (w1 < v1[q] || (w1 == v1[q] && j1 < i1[q])) {
                v1[q] = w1; i1[q] = j1;
            }
        }
    }

    if (tx == 0) {
#pragma unroll
        for (int q = 0; q < 4; ++q) {
            const int lq = ty * 4 + q;
            // Reference dist2 = (z2-2dot)+c2 quantized at ulp(z2+score):
            // within one grid step the reference ties -> argmin takes lower idx.
            const float sfull = z2s[lq] + v0[q];
            const int ebits = (__float_as_int(sfull) >> 23) & 0xff;
            const float u = __int_as_float((ebits - 23) << 23);
            int win = i0[q];
            if (v1[q] - v0[q] <= u && i1[q] < i0[q]) win = i1[q];
            out[q0 + lq] = (float)win;
        }
    }
}

extern "C" void kernel_launch(void* const* d_in, const int* in_sizes, int n_in,
                              void* d_out, int out_size) {
    const float* z  = (const float*)d_in[0];
    const float* cb = (const float*)d_in[1];
    if (n_in >= 2 && in_sizes[0] == KK * DD) {  // defensive order check
        cb = (const float*)d_in[0];
        z  = (const float*)d_in[1];
    }
    vq_kernel<<<NQ / 64, 256>>>(z, cb, (float*)d_out);
}